// round 2
// baseline (speedup 1.0000x reference)
#include <cuda_runtime.h>

// Output is identically zero (g = -sum((x - x)^2) == 0 kills the whole
// pipeline: w = C*g == 0, lambda_tri = mask @ w == 0).
// The 64 KB zero-fill is pure launch-overhead-bound; replace the kernel
// launch with a single native memset node in the captured graph.

extern "C" void kernel_launch(void* const* d_in, const int* in_sizes, int n_in,
                              void* d_out, int out_size) {
    (void)d_in; (void)in_sizes; (void)n_in;
    // out_size float32 elements -> out_size * 4 bytes of zeros.
    cudaMemsetAsync(d_out, 0, (size_t)out_size * sizeof(float));
}